// round 1
// baseline (speedup 1.0000x reference)
#include <cuda_runtime.h>
#include <cuda_bf16.h>

#define N_NODES 50000
#define N_EDGES 800000
#define IN_C    16
#define OUT_C   16
#define EDGE_F  8
// y layout per node: 9 blocks (8 edge-feature blocks + 1 bias block) x 16 outputs
// stored as 36 float4 per node: index = n*36 + f*4 + oq   (oq = output quarter)
#define YB      36

__device__ float4 g_y[N_NODES * YB];   // 28.8 MB scratch (fits L2)

__device__ __forceinline__ void fma4(float4& a, float c, const float4 v) {
    a.x += c * v.x; a.y += c * v.y; a.z += c * v.z; a.w += c * v.w;
}

// ---------------------------------------------------------------------------
// Kernel A: per-node precompute
//   g_y[n][f][o]   = sum_i x[n][i] * w_nn[f][i*16+o]        (f = 0..7)
//   g_y[n][8][o]   = sum_i x[n][i] * b_nn[i*16+o]           (bias block)
//   out[n][o]      = bias[o] + sum_i x[n][i] * root[i][o]   (root term, init for atomics)
// ---------------------------------------------------------------------------
__global__ void node_kernel(const float* __restrict__ x,
                            const float* __restrict__ w_nn,
                            const float* __restrict__ b_nn,
                            const float* __restrict__ root,
                            const float* __restrict__ bias,
                            float* __restrict__ out)
{
    __shared__ float Wsh[9 * 256];      // [f][i*16+o], f==8 holds b_nn
    __shared__ float Rsh[256 + 16];     // root [i][o] + bias[o]

    for (int t = threadIdx.x; t < 2048; t += blockDim.x) Wsh[t] = w_nn[t];
    for (int t = threadIdx.x; t < 256;  t += blockDim.x) Wsh[2048 + t] = b_nn[t];
    for (int t = threadIdx.x; t < 256;  t += blockDim.x) Rsh[t] = root[t];
    for (int t = threadIdx.x; t < 16;   t += blockDim.x) Rsh[256 + t] = bias[t];
    __syncthreads();

    const int gsz  = gridDim.x * blockDim.x;
    const int tid0 = blockIdx.x * blockDim.x + threadIdx.x;

    // ---- y precompute: one float4 of y per task ----
    for (int t = tid0; t < N_NODES * YB; t += gsz) {
        int n  = t / YB;
        int j  = t - n * YB;          // 0..35
        int f  = j >> 2;              // 0..8
        int oq = j & 3;               // output quarter

        const float4* xr = (const float4*)(x + n * IN_C);
        float xv[16];
        #pragma unroll
        for (int ii = 0; ii < 4; ii++) {
            float4 xx = xr[ii];
            xv[4*ii+0] = xx.x; xv[4*ii+1] = xx.y; xv[4*ii+2] = xx.z; xv[4*ii+3] = xx.w;
        }

        const float* wb = &Wsh[f * 256 + oq * 4];
        float4 acc = make_float4(0.f, 0.f, 0.f, 0.f);
        #pragma unroll
        for (int i = 0; i < 16; i++)
            fma4(acc, xv[i], *(const float4*)(wb + i * 16));

        g_y[t] = acc;                 // coalesced: t is linear
    }

    // ---- root term: out[n][oq*4..+3] = bias + x[n] @ root ----
    for (int t = tid0; t < N_NODES * 4; t += gsz) {
        int n  = t >> 2;
        int oq = t & 3;

        const float4* xr = (const float4*)(x + n * IN_C);
        float xv[16];
        #pragma unroll
        for (int ii = 0; ii < 4; ii++) {
            float4 xx = xr[ii];
            xv[4*ii+0] = xx.x; xv[4*ii+1] = xx.y; xv[4*ii+2] = xx.z; xv[4*ii+3] = xx.w;
        }

        float4 acc = *(const float4*)&Rsh[256 + oq * 4];
        #pragma unroll
        for (int i = 0; i < 16; i++)
            fma4(acc, xv[i], *(const float4*)&Rsh[i * 16 + oq * 4]);

        ((float4*)out)[t] = acc;      // out index n*16 + oq*4 == t*4
    }
}

// ---------------------------------------------------------------------------
// Kernel B: per-edge message + scatter-add. 4 threads per edge, each owning
// a float4 of the 16 outputs. Also echoes edge_index (as float) and edge_attr
// into the output buffer when the harness contract includes them.
// ---------------------------------------------------------------------------
__global__ void edge_kernel(const int*   __restrict__ ei,
                            const float* __restrict__ ea,
                            float* __restrict__ out,
                            int echo)
{
    int t = blockIdx.x * blockDim.x + threadIdx.x;
    int e = t >> 2;
    int q = t & 3;
    if (e >= N_EDGES) return;

    int src = ei[e];
    int dst = ei[N_EDGES + e];

    const float4* ea4 = (const float4*)ea;
    float4 a0 = ea4[2 * e];
    float4 a1 = ea4[2 * e + 1];
    float c[8] = {a0.x, a0.y, a0.z, a0.w, a1.x, a1.y, a1.z, a1.w};

    int base = src * YB;
    float4 acc = g_y[base + 32 + q];          // bias block (coef 1)
    #pragma unroll
    for (int f = 0; f < 8; f++)
        fma4(acc, c[f], g_y[base + f * 4 + q]);

    float* o = out + dst * OUT_C + q * 4;
    atomicAdd(o + 0, acc.x);
    atomicAdd(o + 1, acc.y);
    atomicAdd(o + 2, acc.z);
    atomicAdd(o + 3, acc.w);

    if (echo & 1) {   // edge_index echo as float values, [2, E] layout
        if (q == 0) out[N_NODES * OUT_C + e]           = (float)src;
        if (q == 1) out[N_NODES * OUT_C + N_EDGES + e] = (float)dst;
    }
    if (echo & 2) {   // edge_attr echo, [E, 8]
        float2 w;
        if      (q == 0) w = make_float2(a0.x, a0.y);
        else if (q == 1) w = make_float2(a0.z, a0.w);
        else if (q == 2) w = make_float2(a1.x, a1.y);
        else             w = make_float2(a1.z, a1.w);
        ((float2*)(out + N_NODES * OUT_C + 2 * N_EDGES + e * 8))[q] = w;
    }
}

extern "C" void kernel_launch(void* const* d_in, const int* in_sizes, int n_in,
                              void* d_out, int out_size)
{
    const float* x     = (const float*)d_in[0];
    const int*   ei    = (const int*)  d_in[1];
    const float* ea    = (const float*)d_in[2];
    const float* w_nn  = (const float*)d_in[3];
    const float* b_nn  = (const float*)d_in[4];
    const float* root  = (const float*)d_in[5];
    const float* bias  = (const float*)d_in[6];
    float* out = (float*)d_out;

    int echo = 0;
    if (out_size >= N_NODES * OUT_C + 2 * N_EDGES)                        echo |= 1;
    if (out_size >= N_NODES * OUT_C + 2 * N_EDGES + N_EDGES * EDGE_F)     echo |= 2;

    node_kernel<<<2048, 256>>>(x, w_nn, b_nn, root, bias, out);
    edge_kernel<<<(N_EDGES * 4 + 255) / 256, 256>>>(ei, ea, out, echo);
}

// round 3
// speedup vs baseline: 1.5787x; 1.5787x over previous
#include <cuda_runtime.h>
#include <cuda_fp16.h>

#define N_NODES 50000
#define N_EDGES 800000
#define IN_C    16
#define OUT_C   16
#define EDGE_F  8

#define USE_RED_V4 1

// y table in fp16: per node 9 blocks (8 edge-feature + 1 bias) x 16 outputs.
// Stored as uint4 (16 B = 8 halves): index = n*18 + f*2 + h  (h = output half).
// Node stride = 288 B; every (edge,f,h) block is one aligned 16 B access.
#define YU4 18

__device__ __align__(16) uint4 g_yh[N_NODES * YU4];   // 14.4 MB, L2-resident

// ---------------------------------------------------------------------------
// Kernel A: per-node precompute (y table in fp16, root term in fp32)
//          + output echo of edge_index / edge_attr (DRAM streaming work).
// ---------------------------------------------------------------------------
__global__ void node_kernel(const float* __restrict__ x,
                            const int*   __restrict__ ei,
                            const float* __restrict__ ea,
                            const float* __restrict__ w_nn,
                            const float* __restrict__ b_nn,
                            const float* __restrict__ root,
                            const float* __restrict__ bias,
                            float* __restrict__ out,
                            int echo)
{
    __shared__ float Wsh[9 * 256];      // [f][i*16+o], f==8 holds b_nn
    __shared__ float Rsh[256 + 16];     // root [i][o] + bias[o]

    for (int t = threadIdx.x; t < 2048; t += blockDim.x) Wsh[t] = w_nn[t];
    for (int t = threadIdx.x; t < 256;  t += blockDim.x) Wsh[2048 + t] = b_nn[t];
    for (int t = threadIdx.x; t < 256;  t += blockDim.x) Rsh[t] = root[t];
    for (int t = threadIdx.x; t < 16;   t += blockDim.x) Rsh[256 + t] = bias[t];
    __syncthreads();

    const int gsz  = gridDim.x * blockDim.x;
    const int tid0 = blockIdx.x * blockDim.x + threadIdx.x;

    // ---- y precompute: thread = (node, output-half). 9 f-blocks each. ----
    for (int t = tid0; t < N_NODES * 2; t += gsz) {
        int n = t >> 1;
        int h = t & 1;                 // outputs h*8 .. h*8+7

        const float4* xr = (const float4*)(x + n * IN_C);
        float xv[16];
        #pragma unroll
        for (int ii = 0; ii < 4; ii++) {
            float4 xx = xr[ii];
            xv[4*ii+0] = xx.x; xv[4*ii+1] = xx.y; xv[4*ii+2] = xx.z; xv[4*ii+3] = xx.w;
        }

        #pragma unroll
        for (int f = 0; f < 9; f++) {
            const float* wb = &Wsh[f * 256 + h * 8];
            float acc[8];
            #pragma unroll
            for (int o = 0; o < 8; o++) acc[o] = 0.f;
            #pragma unroll
            for (int i = 0; i < 16; i++) {
                float xi = xv[i];
                #pragma unroll
                for (int o = 0; o < 8; o++) acc[o] += xi * wb[i * 16 + o];
            }
            __half2 hv[4];
            #pragma unroll
            for (int j = 0; j < 4; j++)
                hv[j] = __floats2half2_rn(acc[2*j], acc[2*j+1]);
            g_yh[n * YU4 + f * 2 + h] = *(const uint4*)hv;
        }
    }

    // ---- root term init: out[n][oq*4..+3] = bias + x[n] @ root ----
    for (int t = tid0; t < N_NODES * 4; t += gsz) {
        int n  = t >> 2;
        int oq = t & 3;

        const float4* xr = (const float4*)(x + n * IN_C);
        float xv[16];
        #pragma unroll
        for (int ii = 0; ii < 4; ii++) {
            float4 xx = xr[ii];
            xv[4*ii+0] = xx.x; xv[4*ii+1] = xx.y; xv[4*ii+2] = xx.z; xv[4*ii+3] = xx.w;
        }

        float4 acc = *(const float4*)&Rsh[256 + oq * 4];
        #pragma unroll
        for (int i = 0; i < 16; i++) {
            float xi = xv[i];
            const float4 r = *(const float4*)&Rsh[i * 16 + oq * 4];
            acc.x += xi * r.x; acc.y += xi * r.y; acc.z += xi * r.z; acc.w += xi * r.w;
        }
        ((float4*)out)[t] = acc;
    }

    // ---- echoes (streaming, DRAM-bound) ----
    if (echo & 1) {
        for (int t = tid0; t < 2 * N_EDGES; t += gsz)
            out[N_NODES * OUT_C + t] = (float)ei[t];
    }
    if (echo & 2) {
        float4*       dst4 = (float4*)(out + N_NODES * OUT_C + 2 * N_EDGES);
        const float4* src4 = (const float4*)ea;
        for (int t = tid0; t < N_EDGES * 2; t += gsz)
            dst4[t] = src4[t];
    }
}

// ---------------------------------------------------------------------------
// Kernel B: per-edge message + scatter-add. 2 threads per edge, each owning
// 8 of the 16 outputs (fp32 accumulators, fp16 gathers, v4 reductions).
// ---------------------------------------------------------------------------
__global__ void edge_kernel(const int*   __restrict__ ei,
                            const float* __restrict__ ea,
                            float* __restrict__ out)
{
    int t = blockIdx.x * blockDim.x + threadIdx.x;
    int e = t >> 1;
    int h = t & 1;
    if (e >= N_EDGES) return;

    int src = ei[e];
    int dst = ei[N_EDGES + e];

    const float4* ea4 = (const float4*)ea;
    float4 a0 = ea4[2 * e];
    float4 a1 = ea4[2 * e + 1];
    float c[8] = {a0.x, a0.y, a0.z, a0.w, a1.x, a1.y, a1.z, a1.w};

    const uint4* yb = g_yh + src * YU4 + h;

    float acc[8];
    {   // bias block (f = 8), coefficient 1
        uint4 v = yb[16];
        const __half2* hv = (const __half2*)&v;
        #pragma unroll
        for (int j = 0; j < 4; j++) {
            float2 p = __half22float2(hv[j]);
            acc[2*j] = p.x; acc[2*j+1] = p.y;
        }
    }
    #pragma unroll
    for (int f = 0; f < 8; f++) {
        uint4 v = yb[f * 2];
        const __half2* hv = (const __half2*)&v;
        float cf = c[f];
        #pragma unroll
        for (int j = 0; j < 4; j++) {
            float2 p = __half22float2(hv[j]);
            acc[2*j]   += cf * p.x;
            acc[2*j+1] += cf * p.y;
        }
    }

    float* o = out + dst * OUT_C + h * 8;
#if USE_RED_V4 && (__CUDA_ARCH__ >= 900)
    asm volatile("red.global.add.v4.f32 [%0], {%1, %2, %3, %4};"
                 :: "l"(o),     "f"(acc[0]), "f"(acc[1]), "f"(acc[2]), "f"(acc[3])
                 : "memory");
    asm volatile("red.global.add.v4.f32 [%0], {%1, %2, %3, %4};"
                 :: "l"(o + 4), "f"(acc[4]), "f"(acc[5]), "f"(acc[6]), "f"(acc[7])
                 : "memory");
#else
    #pragma unroll
    for (int j = 0; j < 8; j++) atomicAdd(o + j, acc[j]);
#endif
}

extern "C" void kernel_launch(void* const* d_in, const int* in_sizes, int n_in,
                              void* d_out, int out_size)
{
    const float* x     = (const float*)d_in[0];
    const int*   ei    = (const int*)  d_in[1];
    const float* ea    = (const float*)d_in[2];
    const float* w_nn  = (const float*)d_in[3];
    const float* b_nn  = (const float*)d_in[4];
    const float* root  = (const float*)d_in[5];
    const float* bias  = (const float*)d_in[6];
    float* out = (float*)d_out;

    int echo = 0;
    if (out_size >= N_NODES * OUT_C + 2 * N_EDGES)                        echo |= 1;
    if (out_size >= N_NODES * OUT_C + 2 * N_EDGES + N_EDGES * EDGE_F)     echo |= 2;

    node_kernel<<<1024, 256>>>(x, ei, ea, w_nn, b_nn, root, bias, out, echo);
    edge_kernel<<<(N_EDGES * 2 + 255) / 256, 256>>>(ei, ea, out);
}